// round 2
// baseline (speedup 1.0000x reference)
#include <cuda_runtime.h>
#include <cuda_bf16.h>
#include <cstdint>

#define S_DIM 16
#define P_DIM 65536
#define N_DIM 256
#define K_DIM 32

// One block per (channel, row) pair: 3 * 256 = 768 blocks.
// Phase 1: zero the 65536-float row with coalesced float4 stores.
// Phase 2 (after __syncthreads): warp 0 overwrites the <=32 hot entries
// for this row/channel.
__global__ void __launch_bounds__(256, 4)
fused_kernel(const float4* __restrict__ schema_params, // [S, P] float4
             const int* __restrict__ schema_ids,       // [N]
             const int* __restrict__ indices,          // [N, K]
             float* __restrict__ out)                  // [3, N, P]
{
    const int row = blockIdx.x;        // 0..767
    const int c   = row >> 8;          // channel 0..2
    const int n   = row & 255;         // row 0..255

    float4* row_out = (float4*)(out + (size_t)row * P_DIM);

    // ---- Phase 1: zero fill (16384 float4, 64 per thread, coalesced) ----
    const float4 z = make_float4(0.f, 0.f, 0.f, 0.f);
    int t = threadIdx.x;
#pragma unroll 8
    for (int i = 0; i < P_DIM / 4; i += 256) {
        row_out[i + t] = z;
    }

    __syncthreads();   // cta-scope fence: orders the zeros before phase-2 writes

    // ---- Phase 2: scatter hot entries (warp 0 only) ----
    if (threadIdx.x < 32) {
        const int lane = threadIdx.x;
        const int p    = indices[n * K_DIM + lane];
        const int sid  = schema_ids[n];

        unsigned mask   = __match_any_sync(0xffffffffu, p);
        int      count  = __popc(mask);
        bool     leader = (lane == (__ffs(mask) - 1));

        if (leader) {
            float4 sp = schema_params[(size_t)sid * P_DIM + p];
            // proj rows: c0 = f2+f3, c1 = f1, c2 = f3
            float v = (c == 0) ? (sp.z + sp.w) : (c == 1) ? sp.y : sp.w;
            float b = 1.0f - v;
            float r = b;
            for (int i = 1; i < count; i++) r *= b;
            out[(size_t)row * P_DIM + p] = 1.0f - r;
        }
    }
}

extern "C" void kernel_launch(void* const* d_in, const int* in_sizes, int n_in,
                              void* d_out, int out_size) {
    const float4* schema_params = (const float4*)d_in[0];   // (16, 65536, 4) fp32
    const int*    schema_ids    = (const int*)d_in[1];      // (256,)
    const int*    indices       = (const int*)d_in[2];      // (256, 32)
    float*        out           = (float*)d_out;            // (3, 256, 65536) fp32

    fused_kernel<<<3 * N_DIM, 256>>>(schema_params, schema_ids, indices, out);
}

// round 3
// speedup vs baseline: 1.1381x; 1.1381x over previous
#include <cuda_runtime.h>
#include <cuda_bf16.h>
#include <cstdint>

#define S_DIM 16
#define P_DIM 65536
#define N_DIM 256
#define K_DIM 32

// 16 segments per (channel,row): grid = 3*256*16 = 12288 CTAs.
// Each CTA zeroes a 4096-float segment (4 x float4 per thread) and then
// scatters the hot entries of its row that fall inside its segment.
// Writes are disjoint across CTAs; intra-CTA order via __syncthreads.
#define SEGS_PER_ROW 16
#define SEG_FLOATS   (P_DIM / SEGS_PER_ROW)   // 4096

__global__ void fused_kernel(const float4* __restrict__ schema_params, // [S, P] float4
                             const int* __restrict__ schema_ids,       // [N]
                             const int* __restrict__ indices,          // [N, K]
                             float* __restrict__ out)                  // [3, N, P]
{
    const int bid = blockIdx.x;
    const int seg = bid & (SEGS_PER_ROW - 1);
    const int row = bid >> 4;           // 0..767
    const int c   = row >> 8;           // channel 0..2
    const int n   = row & 255;          // row 0..255

    const int seg_lo = seg * SEG_FLOATS;

    // ---- Phase 1: zero this segment (1024 float4, 4 per thread) ----
    float4* seg_out = (float4*)(out + (size_t)row * P_DIM + seg_lo);
    const float4 z = make_float4(0.f, 0.f, 0.f, 0.f);
    const int t = threadIdx.x;
    seg_out[t]       = z;
    seg_out[t + 256] = z;
    seg_out[t + 512] = z;
    seg_out[t + 768] = z;

    __syncthreads();   // order zeros before scatter within this CTA

    // ---- Phase 2: scatter hot entries landing in this segment (warp 0) ----
    if (t < 32) {
        const int p   = indices[n * K_DIM + t];
        const bool in_seg = ((unsigned)(p - seg_lo) < (unsigned)SEG_FLOATS);

        unsigned mask   = __match_any_sync(0xffffffffu, p);
        int      count  = __popc(mask);
        bool     leader = (t == (__ffs(mask) - 1));

        if (leader && in_seg) {
            const int sid = schema_ids[n];
            float4 sp = schema_params[(size_t)sid * P_DIM + p];
            // proj rows: c0 = f2+f3, c1 = f1, c2 = f3
            float v = (c == 0) ? (sp.z + sp.w) : (c == 1) ? sp.y : sp.w;
            float b = 1.0f - v;
            float r = b;
            for (int i = 1; i < count; i++) r *= b;
            out[(size_t)row * P_DIM + p] = 1.0f - r;
        }
    }
}

extern "C" void kernel_launch(void* const* d_in, const int* in_sizes, int n_in,
                              void* d_out, int out_size) {
    const float4* schema_params = (const float4*)d_in[0];   // (16, 65536, 4) fp32
    const int*    schema_ids    = (const int*)d_in[1];      // (256,)
    const int*    indices       = (const int*)d_in[2];      // (256, 32)
    float*        out           = (float*)d_out;            // (3, 256, 65536) fp32

    fused_kernel<<<3 * N_DIM * SEGS_PER_ROW, 256>>>(schema_params, schema_ids, indices, out);
}

// round 4
// speedup vs baseline: 1.1567x; 1.0163x over previous
#include <cuda_runtime.h>
#include <cuda_bf16.h>
#include <cstdint>

#define S_DIM 16
#define P_DIM 65536
#define N_DIM 256
#define K_DIM 32

// CTA = 256 threads = 8 independent warps. Each warp owns a contiguous
// 1024-float range of one (channel,row): zeroes it, then scatters the hot
// entries that fall inside that range. No cross-warp aliasing -> only
// __syncwarp() needed (PTX bar.warp.sync guarantees memory ordering among
// the warp's lanes).
//
// CTA covers 8192 floats -> 8 CTAs per 65536-float row.
// grid = 3 * 256 * 8 = 6144 CTAs.
#define CTA_FLOATS  8192
#define WARP_FLOATS 1024

__global__ void __launch_bounds__(256)
fused_kernel(const float4* __restrict__ schema_params, // [S, P] float4
             const int* __restrict__ schema_ids,       // [N]
             const int* __restrict__ indices,          // [N, K]
             float* __restrict__ out)                  // [3, N, P]
{
    const int bid  = blockIdx.x;
    const int seg  = bid & 7;           // which 8192-float chunk of the row
    const int row  = bid >> 3;          // 0..767
    const int c    = row >> 8;          // channel 0..2
    const int n    = row & 255;         // row 0..255
    const int warp = threadIdx.x >> 5;
    const int lane = threadIdx.x & 31;

    // Warp's float range within the row
    const int range_lo = seg * CTA_FLOATS + warp * WARP_FLOATS;

    // ---- Prefetch: issue the dependent loads FIRST so their latency hides
    //      under the zero-fill stores below.
    const int p   = indices[n * K_DIM + lane];   // LDG issued here
    const int sid = schema_ids[n];               // L2-resident

    // ---- Phase 1: zero fill this warp's 1024 floats (8 float4 per lane,
    //      512B contiguous per warp-instruction).
    float4* wout = (float4*)(out + (size_t)row * P_DIM + range_lo);
    const float4 z = make_float4(0.f, 0.f, 0.f, 0.f);
#pragma unroll
    for (int j = 0; j < WARP_FLOATS / 4 / 32; j++) {
        wout[lane + 32 * j] = z;
    }

    __syncwarp();   // execution + memory ordering among this warp's lanes

    // ---- Phase 2: scatter hot entries landing in this warp's range.
    const bool in_range = ((unsigned)(p - range_lo) < (unsigned)WARP_FLOATS);

    unsigned mask   = __match_any_sync(0xffffffffu, p);
    int      count  = __popc(mask);
    bool     leader = (lane == (__ffs(mask) - 1));

    if (leader && in_range) {
        float4 sp = schema_params[(size_t)sid * P_DIM + p];
        // proj rows: c0 = f2+f3, c1 = f1, c2 = f3
        float v = (c == 0) ? (sp.z + sp.w) : (c == 1) ? sp.y : sp.w;
        float b = 1.0f - v;
        float r = b;
        for (int i = 1; i < count; i++) r *= b;
        out[(size_t)row * P_DIM + p] = 1.0f - r;
    }
}

extern "C" void kernel_launch(void* const* d_in, const int* in_sizes, int n_in,
                              void* d_out, int out_size) {
    const float4* schema_params = (const float4*)d_in[0];   // (16, 65536, 4) fp32
    const int*    schema_ids    = (const int*)d_in[1];      // (256,)
    const int*    indices       = (const int*)d_in[2];      // (256, 32)
    float*        out           = (float*)d_out;            // (3, 256, 65536) fp32

    const int blocks = 3 * N_DIM * (P_DIM / CTA_FLOATS);    // 6144
    fused_kernel<<<blocks, 256>>>(schema_params, schema_ids, indices, out);
}

// round 5
// speedup vs baseline: 1.1590x; 1.0019x over previous
#include <cuda_runtime.h>
#include <cuda_bf16.h>
#include <cstdint>

#define S_DIM 16
#define P_DIM 65536
#define N_DIM 256
#define K_DIM 32

// Warp-granular fused fill+scatter.
// Each warp owns a contiguous 2048-float range of one (channel,row):
// zeroes it with streaming (evict-first) float4 stores, then scatters the
// hot entries that fall inside its range. Cross-warp writes never alias,
// so only __syncwarp() is needed.
//
// CTA = 8 warps = 16384 floats -> 4 CTAs per 65536-float row.
// grid = 3 * 256 * 4 = 3072 CTAs.
#define WARP_FLOATS 2048
#define CTA_FLOATS  (WARP_FLOATS * 8)     // 16384
#define VEC_PER_LANE (WARP_FLOATS / 4 / 32) // 16

__global__ void __launch_bounds__(256)
fused_kernel(const float4* __restrict__ schema_params, // [S, P] float4
             const int* __restrict__ schema_ids,       // [N]
             const int* __restrict__ indices,          // [N, K]
             float* __restrict__ out)                  // [3, N, P]
{
    const int bid  = blockIdx.x;
    const int seg  = bid & 3;           // which 16384-float chunk of the row
    const int row  = bid >> 2;          // 0..767
    const int c    = row >> 8;          // channel 0..2
    const int n    = row & 255;         // row 0..255
    const int warp = threadIdx.x >> 5;
    const int lane = threadIdx.x & 31;

    const int range_lo = seg * CTA_FLOATS + warp * WARP_FLOATS;

    // Prefetch the index this lane owns; latency hides under the fill stores.
    const int p = __ldg(&indices[n * K_DIM + lane]);

    // ---- Phase 1: zero fill, streaming stores (evict-first in L2) ----
    float4* wout = (float4*)(out + (size_t)row * P_DIM + range_lo);
    const float4 z = make_float4(0.f, 0.f, 0.f, 0.f);
#pragma unroll
    for (int j = 0; j < VEC_PER_LANE; j++) {
        __stcs(&wout[lane + 32 * j], z);
    }

    __syncwarp();   // order this warp's zeros before its scatter writes

    // ---- Phase 2: scatter hot entries landing in this warp's range ----
    const bool in_range = ((unsigned)(p - range_lo) < (unsigned)WARP_FLOATS);

    unsigned mask   = __match_any_sync(0xffffffffu, p);
    int      count  = __popc(mask);
    bool     leader = (lane == (__ffs(mask) - 1));

    if (leader && in_range) {
        const int sid = __ldg(&schema_ids[n]);
        float4 sp = __ldg(&schema_params[(size_t)sid * P_DIM + p]);
        // proj rows: c0 = f2+f3, c1 = f1, c2 = f3
        float v = (c == 0) ? (sp.z + sp.w) : (c == 1) ? sp.y : sp.w;
        float b = 1.0f - v;
        float r = b;
        for (int i = 1; i < count; i++) r *= b;
        out[(size_t)row * P_DIM + p] = 1.0f - r;
    }
}

extern "C" void kernel_launch(void* const* d_in, const int* in_sizes, int n_in,
                              void* d_out, int out_size) {
    const float4* schema_params = (const float4*)d_in[0];   // (16, 65536, 4) fp32
    const int*    schema_ids    = (const int*)d_in[1];      // (256,)
    const int*    indices       = (const int*)d_in[2];      // (256, 32)
    float*        out           = (float*)d_out;            // (3, 256, 65536) fp32

    const int blocks = 3 * N_DIM * (P_DIM / CTA_FLOATS);    // 3072
    fused_kernel<<<blocks, 256>>>(schema_params, schema_ids, indices, out);
}